// round 4
// baseline (speedup 1.0000x reference)
#include <cuda_runtime.h>
#include <cstdint>

// ============================================================================
// AdditiveAttention fused kernels for GB300 (sm_103a) — Round 4
//   proj: BM=32 (320 blocks), packed fma.rn.f32x2 inner product, double-buffer
//   attn: split-K (S=8) + cp.async double-buffered K/V tiles
// ============================================================================

#define NEG_FILL (-1e6f)
#define S_SPLIT 8
#define QT 8
#define KT 32
#define KP 132

typedef unsigned long long ull;

// Scratch (allocation-free: __device__ globals)
__device__ float g_qh[8 * 256 * 128];                 // 1 MB
__device__ float g_kh[8 * 1024 * 128];                // 4 MB
__device__ float g_po[S_SPLIT * 2048 * 128];          // 8 MB partial o
__device__ float g_pl[S_SPLIT * 2048];                // 64 KB partial l

__device__ __forceinline__ float fast_tanh(float x) {
    float y;
    asm("tanh.approx.f32 %0, %1;" : "=f"(y) : "f"(x));
    return y;
}
__device__ __forceinline__ ull pack2(float x, float y) {
    ull r; asm("mov.b64 %0, {%1, %2};" : "=l"(r) : "f"(x), "f"(y)); return r;
}
__device__ __forceinline__ float2 unpack2(ull v) {
    float2 r; asm("mov.b64 {%0, %1}, %2;" : "=f"(r.x), "=f"(r.y) : "l"(v)); return r;
}
__device__ __forceinline__ void fma2(ull& acc, ull a, ull b) {
    asm("fma.rn.f32x2 %0, %1, %2, %0;" : "+l"(acc) : "l"(a), "l"(b));
}
__device__ __forceinline__ void cp16(uint32_t s, const void* g) {
    asm volatile("cp.async.cg.shared.global [%0], [%1], 16;" :: "r"(s), "l"(g));
}
#define CP_COMMIT() asm volatile("cp.async.commit_group;")
#define CP_WAIT0()  asm volatile("cp.async.wait_group 0;")

// ----------------------------------------------------------------------------
// Projection GEMM: Y[rows,128] = X[rows,256] @ W[256,128]
// BM=32, BN=128, BK=16; 256 threads, 2x8 outputs/thread via 8 FFMA2 per k.
// blocks 0..63 -> q rows (2048), 64..319 -> k rows (8192, masked blocks skip).
// ----------------------------------------------------------------------------
__global__ __launch_bounds__(256) void proj_kernel(
    const float* __restrict__ Xq, const float* __restrict__ Xk,
    const float* __restrict__ Wq, const float* __restrict__ Wk,
    const int* __restrict__ valid_lens)
{
    int bx = blockIdx.x;
    const float* X; const float* W; float* Y; int row0;
    if (bx < 64) {
        X = Xq; W = Wq; Y = g_qh; row0 = bx << 5;
    } else {
        int kb = bx - 64;               // 0..255, 32 per batch
        int b  = kb >> 5;
        if (((kb & 31) << 5) >= valid_lens[b]) return;  // never read downstream
        X = Xk; W = Wk; Y = g_kh; row0 = kb << 5;
    }

    __shared__ float Xs[2][32][18];     // row-major X tile, padded
    __shared__ float Ws[2][16][128];    // [k][col]          (total ~20.5 KB)

    int tid = threadIdx.x;
    int tx = tid & 15;      // col group: cols tx*8 .. tx*8+7
    int ty = tid >> 4;      // row pair:  rows ty*2, ty*2+1

    // load mapping
    int xr = tid >> 3;              // 0..31
    int xc = (tid & 7) << 1;        // 0..14 (even)
    int wr = tid >> 5;              // 0..7
    int wc = (tid & 31) << 2;       // 0..124

    const float* Xp  = &X[(row0 + xr) * 256 + xc];
    const float* Wp0 = &W[wr * 128 + wc];
    const float* Wp1 = &W[(wr + 8) * 128 + wc];

    ull acc[2][4];
#pragma unroll
    for (int i = 0; i < 2; i++)
#pragma unroll
        for (int j = 0; j < 4; j++) acc[i][j] = pack2(0.f, 0.f);

    // prologue: tile 0 -> buf 0
    float2 xv  = *(const float2*)Xp;
    float4 wv0 = *(const float4*)Wp0;
    float4 wv1 = *(const float4*)Wp1;
    *(float2*)&Xs[0][xr][xc] = xv;
    *(float4*)&Ws[0][wr][wc]     = wv0;
    *(float4*)&Ws[0][wr + 8][wc] = wv1;
    __syncthreads();

    for (int it = 0; it < 16; it++) {
        int buf = it & 1;
        if (it < 15) {  // prefetch next k-tile into registers
            int k0 = (it + 1) << 4;
            xv  = *(const float2*)(Xp + k0);
            wv0 = *(const float4*)(Wp0 + k0 * 128);
            wv1 = *(const float4*)(Wp1 + k0 * 128);
        }
#pragma unroll
        for (int k = 0; k < 16; k++) {
            float a0 = Xs[buf][ty * 2][k];
            float a1 = Xs[buf][ty * 2 + 1][k];
            float4 b0 = *(float4*)&Ws[buf][k][tx * 8];
            float4 b1 = *(float4*)&Ws[buf][k][tx * 8 + 4];
            ull B0 = pack2(b0.x, b0.y), B1 = pack2(b0.z, b0.w);
            ull B2 = pack2(b1.x, b1.y), B3 = pack2(b1.z, b1.w);
            ull A0 = pack2(a0, a0),     A1 = pack2(a1, a1);
            fma2(acc[0][0], A0, B0); fma2(acc[0][1], A0, B1);
            fma2(acc[0][2], A0, B2); fma2(acc[0][3], A0, B3);
            fma2(acc[1][0], A1, B0); fma2(acc[1][1], A1, B1);
            fma2(acc[1][2], A1, B2); fma2(acc[1][3], A1, B3);
        }
        if (it < 15) {
            int nb = buf ^ 1;
            *(float2*)&Xs[nb][xr][xc] = xv;
            *(float4*)&Ws[nb][wr][wc]     = wv0;
            *(float4*)&Ws[nb][wr + 8][wc] = wv1;
        }
        __syncthreads();
    }

#pragma unroll
    for (int i = 0; i < 2; i++) {
        float2 c0 = unpack2(acc[i][0]), c1 = unpack2(acc[i][1]);
        float2 c2 = unpack2(acc[i][2]), c3 = unpack2(acc[i][3]);
        int r = row0 + ty * 2 + i;
        float4 o0 = {c0.x, c0.y, c1.x, c1.y};
        float4 o1 = {c2.x, c2.y, c3.x, c3.y};
        *(float4*)&Y[r * 128 + tx * 8]     = o0;
        *(float4*)&Y[r * 128 + tx * 8 + 4] = o1;
    }
}

// ----------------------------------------------------------------------------
// Split-K score + exp + AV partial kernel, cp.async double-buffered.
// grid = (Q/QT, B, S_SPLIT), 256 threads (8 warps, warp-per-q-row, lane-per-k).
// Dynamic smem layout (floats):
//   ks[2][32][132] @ 0      vs[2][32][128] @ 8448
//   qs[8][128] @ 16640      wv[128] @ 17664     total 71168 B
// ----------------------------------------------------------------------------
#define ATTN_SMEM_BYTES 71168

__global__ __launch_bounds__(256) void attn_partial_kernel(
    const float* __restrict__ V, const int* __restrict__ valid_lens,
    const float* __restrict__ w_v)
{
    extern __shared__ float sm[];
    float* qs = sm + 16640;
    float* wv = sm + 17664;

    int b    = blockIdx.y;
    int q0   = blockIdx.x * QT;
    int sp   = blockIdx.z;
    int tid  = threadIdx.x;
    int w    = tid >> 5;
    int lane = tid & 31;
    int nv   = valid_lens[b];          // 1..1024
    int ntiles = (nv + 31) >> 5;

    uint32_t su = (uint32_t)__cvta_generic_to_shared(sm);

    int lr = tid >> 3;                 // 0..31
    int lc = (tid & 7) << 2;           // float col base
    const float* gkb = g_kh + ((size_t)(b << 10) + lr) * 128 + lc;
    const float* gvb = V    + ((size_t)(b << 10) + lr) * 128 + lc;
    uint32_t ku0 = su + (uint32_t)(lr * KP  + lc) * 4u;
    uint32_t vu0 = su + (uint32_t)(8448 + lr * 128 + lc) * 4u;

    // prologue: issue tile sp into buf 0
    if (sp < ntiles) {
        const float* gk = gkb + (sp << 5) * 128;
        const float* gv = gvb + (sp << 5) * 128;
#pragma unroll
        for (int j = 0; j < 4; j++) {
            cp16(ku0 + j * 128u, gk + (j << 3) * 4);
            cp16(vu0 + j * 128u, gv + (j << 3) * 4);
        }
    }
    CP_COMMIT();

    // stage q rows + w_v (overlaps with cp.async)
    {
        int r = tid >> 5;
        int c = lane << 2;
        *(float4*)&qs[r * 128 + c] =
            *(const float4*)&g_qh[((b << 8) + q0 + r) * 128 + c];
    }
    if (tid < 128) wv[tid] = w_v[tid];

    float  l = 0.f;
    float4 o = {0.f, 0.f, 0.f, 0.f};

    int buf = 0;
    for (int t = sp; t < ntiles; t += S_SPLIT, buf ^= 1) {
        CP_WAIT0();
        __syncthreads();

        int tn = t + S_SPLIT;
        if (tn < ntiles) {
            uint32_t koff = (buf ^ 1) ? 0x4200u : 0u;   // 4224 floats
            uint32_t voff = (buf ^ 1) ? 0x4000u : 0u;   // 4096 floats
            const float* gk = gkb + (tn << 5) * 128;
            const float* gv = gvb + (tn << 5) * 128;
#pragma unroll
            for (int j = 0; j < 4; j++) {
                cp16(ku0 + koff + j * 128u, gk + (j << 3) * 4);
                cp16(vu0 + voff + j * 128u, gv + (j << 3) * 4);
            }
        }
        CP_COMMIT();

        // ---- score for k = (t<<5) + lane, q row q0 + w ----
        const float* ksp = sm + buf * 4224 + lane * KP;
        const float* qsp = qs + w * 128;
        float s = 0.f;
#pragma unroll
        for (int h = 0; h < 128; h += 4) {
            float4 kv = *(float4*)&ksp[h];
            float4 qv = *(float4*)&qsp[h];
            float4 w4 = *(float4*)&wv[h];
            s += fast_tanh(qv.x + kv.x) * w4.x;
            s += fast_tanh(qv.y + kv.y) * w4.y;
            s += fast_tanh(qv.z + kv.z) * w4.z;
            s += fast_tanh(qv.w + kv.w) * w4.w;
        }
        if ((t << 5) + lane >= nv) s = NEG_FILL;   // exp -> exactly 0

        float p = __expf(s);
        l += p;

        // ---- AV: lane owns output dims lane*4 .. lane*4+3 ----
        const float* vsp = sm + 8448 + buf * 4096;
#pragma unroll
        for (int k = 0; k < KT; k++) {
            float  pk = __shfl_sync(0xffffffffu, p, k);
            float4 vv = *(float4*)&vsp[k * 128 + (lane << 2)];
            o.x += pk * vv.x; o.y += pk * vv.y;
            o.z += pk * vv.z; o.w += pk * vv.w;
        }
    }

#pragma unroll
    for (int off = 16; off; off >>= 1)
        l += __shfl_xor_sync(0xffffffffu, l, off);

    int row = (b << 8) + q0 + w;
    if (lane == 0) g_pl[sp * 2048 + row] = l;
    *(float4*)&g_po[(sp * 2048 + row) * 128 + (lane << 2)] = o;
}

// ----------------------------------------------------------------------------
// Combine partials: out[row,:] = sum_s o_s / sum_s l_s
// ----------------------------------------------------------------------------
__global__ __launch_bounds__(256) void combine_kernel(float* __restrict__ out)
{
    int idx = blockIdx.x * 256 + threadIdx.x;   // 0 .. 65535
    int row = idx >> 5;
    int c   = (idx & 31) << 2;

    float  l = 0.f;
    float4 a = {0.f, 0.f, 0.f, 0.f};
#pragma unroll
    for (int s = 0; s < S_SPLIT; s++) {
        l += g_pl[s * 2048 + row];
        float4 v = *(const float4*)&g_po[(s * 2048 + row) * 128 + c];
        a.x += v.x; a.y += v.y; a.z += v.z; a.w += v.w;
    }
    float inv = 1.0f / l;
    a.x *= inv; a.y *= inv; a.z *= inv; a.w *= inv;
    *(float4*)&out[row * 128 + c] = a;
}

// ----------------------------------------------------------------------------
// Launch
// ----------------------------------------------------------------------------
extern "C" void kernel_launch(void* const* d_in, const int* in_sizes, int n_in,
                              void* d_out, int out_size)
{
    const float* queries    = (const float*)d_in[0];  // [8,256,256]
    const float* keys       = (const float*)d_in[1];  // [8,1024,256]
    const float* values     = (const float*)d_in[2];  // [8,1024,128]
    const int*   valid_lens = (const int*)  d_in[3];  // [8]
    const float* W_q        = (const float*)d_in[4];  // [256,128]
    const float* W_k        = (const float*)d_in[5];  // [256,128]
    const float* w_v        = (const float*)d_in[6];  // [128]
    float*       out        = (float*)d_out;          // [8,256,128]

    cudaFuncSetAttribute(attn_partial_kernel,
                         cudaFuncAttributeMaxDynamicSharedMemorySize,
                         ATTN_SMEM_BYTES);

    proj_kernel<<<320, 256>>>(queries, keys, W_q, W_k, valid_lens);

    dim3 grid(256 / QT, 8, S_SPLIT);
    attn_partial_kernel<<<grid, 256, ATTN_SMEM_BYTES>>>(values, valid_lens, w_v);

    combine_kernel<<<256, 256>>>(out);
}

// round 5
// speedup vs baseline: 1.2097x; 1.2097x over previous
#include <cuda_runtime.h>
#include <cstdint>

// ============================================================================
// AdditiveAttention fused kernels for GB300 (sm_103a) — Round 5
//   proj: scalar-FFMA microkernel (R3 shape), 512 threads/block for 4 w/SMSP,
//         conflict-free B reads (tx*4 / tx*4+64 split)
//   attn: split-K (S=8) + cp.async double-buffered K/V tiles (unchanged)
// ============================================================================

#define NEG_FILL (-1e6f)
#define S_SPLIT 8
#define QT 8
#define KT 32
#define KP 132

// Scratch (allocation-free: __device__ globals)
__device__ float g_qh[8 * 256 * 128];                 // 1 MB
__device__ float g_kh[8 * 1024 * 128];                // 4 MB
__device__ float g_po[S_SPLIT * 2048 * 128];          // 8 MB partial o
__device__ float g_pl[S_SPLIT * 2048];                // 64 KB partial l

__device__ __forceinline__ float fast_tanh(float x) {
    float y;
    asm("tanh.approx.f32 %0, %1;" : "=f"(y) : "f"(x));
    return y;
}
__device__ __forceinline__ void cp16(uint32_t s, const void* g) {
    asm volatile("cp.async.cg.shared.global [%0], [%1], 16;" :: "r"(s), "l"(g));
}
#define CP_COMMIT() asm volatile("cp.async.commit_group;")
#define CP_WAIT0()  asm volatile("cp.async.wait_group 0;")

// ----------------------------------------------------------------------------
// Projection GEMM: Y[rows,128] = X[rows,256] @ W[256,128]
// BM=64, BN=128, BK=16, 512 threads (16 warps -> 4 warps/SMSP at 1 block/SM).
// Each thread: 2 rows x 8 cols (cols tx*4..+3 and tx*4+64..+67).
// blocks 0..31 -> q rows, 32..159 -> k rows (masked blocks exit).
// Double-buffered smem with register prefetch; one sync per k-tile.
// ----------------------------------------------------------------------------
__global__ __launch_bounds__(512) void proj_kernel(
    const float* __restrict__ Xq, const float* __restrict__ Xk,
    const float* __restrict__ Wq, const float* __restrict__ Wk,
    const int* __restrict__ valid_lens)
{
    int bx = blockIdx.x;
    const float* X; const float* W; float* Y; int row0;
    if (bx < 32) {
        X = Xq; W = Wq; Y = g_qh; row0 = bx << 6;
    } else {
        int kb = bx - 32;               // 0..127, 16 per batch
        int b  = kb >> 4;
        if (((kb & 15) << 6) >= valid_lens[b]) return;  // never read downstream
        X = Xk; W = Wk; Y = g_kh; row0 = kb << 6;
    }

    __shared__ float Xs[2][16][64];     // [buf][k][row] transposed, 8 KB
    __shared__ float Ws[2][16][128];    // [buf][k][col], 16 KB

    int tid = threadIdx.x;
    int tx = tid & 15;      // col group
    int ty = tid >> 4;      // 0..31 -> rows ty*2, ty*2+1

    // load lane mapping
    int xr = tid >> 3;              // 0..63
    int xc = (tid & 7) << 1;        // 0..14 (even)
    int wr = tid >> 5;              // 0..15
    int wc = (tid & 31) << 2;       // 0..124

    const float* Xp = &X[(row0 + xr) * 256 + xc];
    const float* Wp = &W[wr * 128 + wc];

    float acc[2][8];
#pragma unroll
    for (int i = 0; i < 2; i++)
#pragma unroll
        for (int j = 0; j < 8; j++) acc[i][j] = 0.f;

    // prologue: tile 0 -> buf 0
    float2 xv = *(const float2*)Xp;
    float4 wv = *(const float4*)Wp;
    Xs[0][xc][xr] = xv.x; Xs[0][xc + 1][xr] = xv.y;
    *(float4*)&Ws[0][wr][wc] = wv;
    __syncthreads();

    for (int it = 0; it < 16; it++) {
        int buf = it & 1;
        if (it < 15) {  // prefetch next k-tile into registers
            int k0 = (it + 1) << 4;
            xv = *(const float2*)(Xp + k0);
            wv = *(const float4*)(Wp + k0 * 128);
        }
#pragma unroll
        for (int k = 0; k < 16; k++) {
            float a0 = Xs[buf][k][ty * 2];
            float a1 = Xs[buf][k][ty * 2 + 1];
            float4 b0 = *(float4*)&Ws[buf][k][tx * 4];        // banks 0..31
            float4 b1 = *(float4*)&Ws[buf][k][tx * 4 + 64];   // banks 0..31
            float bv[8] = {b0.x, b0.y, b0.z, b0.w, b1.x, b1.y, b1.z, b1.w};
#pragma unroll
            for (int j = 0; j < 8; j++) {
                acc[0][j] += a0 * bv[j];
                acc[1][j] += a1 * bv[j];
            }
        }
        if (it < 15) {
            int nb = buf ^ 1;
            Xs[nb][xc][xr] = xv.x; Xs[nb][xc + 1][xr] = xv.y;
            *(float4*)&Ws[nb][wr][wc] = wv;
        }
        __syncthreads();
    }

#pragma unroll
    for (int i = 0; i < 2; i++) {
        int r = row0 + ty * 2 + i;
        float4 o0 = {acc[i][0], acc[i][1], acc[i][2], acc[i][3]};
        float4 o1 = {acc[i][4], acc[i][5], acc[i][6], acc[i][7]};
        *(float4*)&Y[r * 128 + tx * 4]      = o0;
        *(float4*)&Y[r * 128 + tx * 4 + 64] = o1;
    }
}

// ----------------------------------------------------------------------------
// Split-K score + exp + AV partial kernel, cp.async double-buffered.
// grid = (Q/QT, B, S_SPLIT), 256 threads (8 warps, warp-per-q-row, lane-per-k).
// Dynamic smem layout (floats):
//   ks[2][32][132] @ 0      vs[2][32][128] @ 8448
//   qs[8][128] @ 16640      wv[128] @ 17664     total 71168 B
// ----------------------------------------------------------------------------
#define ATTN_SMEM_BYTES 71168

__global__ __launch_bounds__(256) void attn_partial_kernel(
    const float* __restrict__ V, const int* __restrict__ valid_lens,
    const float* __restrict__ w_v)
{
    extern __shared__ float sm[];
    float* qs = sm + 16640;
    float* wv = sm + 17664;

    int b    = blockIdx.y;
    int q0   = blockIdx.x * QT;
    int sp   = blockIdx.z;
    int tid  = threadIdx.x;
    int w    = tid >> 5;
    int lane = tid & 31;
    int nv   = valid_lens[b];          // 1..1024
    int ntiles = (nv + 31) >> 5;

    uint32_t su = (uint32_t)__cvta_generic_to_shared(sm);

    int lr = tid >> 3;                 // 0..31
    int lc = (tid & 7) << 2;           // float col base
    const float* gkb = g_kh + ((size_t)(b << 10) + lr) * 128 + lc;
    const float* gvb = V    + ((size_t)(b << 10) + lr) * 128 + lc;
    uint32_t ku0 = su + (uint32_t)(lr * KP  + lc) * 4u;
    uint32_t vu0 = su + (uint32_t)(8448 + lr * 128 + lc) * 4u;

    // prologue: issue tile sp into buf 0
    if (sp < ntiles) {
        const float* gk = gkb + (sp << 5) * 128;
        const float* gv = gvb + (sp << 5) * 128;
#pragma unroll
        for (int j = 0; j < 4; j++) {
            cp16(ku0 + j * 128u, gk + (j << 3) * 4);
            cp16(vu0 + j * 128u, gv + (j << 3) * 4);
        }
    }
    CP_COMMIT();

    // stage q rows + w_v (overlaps with cp.async)
    {
        int r = tid >> 5;
        int c = lane << 2;
        *(float4*)&qs[r * 128 + c] =
            *(const float4*)&g_qh[((b << 8) + q0 + r) * 128 + c];
    }
    if (tid < 128) wv[tid] = w_v[tid];

    float  l = 0.f;
    float4 o = {0.f, 0.f, 0.f, 0.f};

    int buf = 0;
    for (int t = sp; t < ntiles; t += S_SPLIT, buf ^= 1) {
        CP_WAIT0();
        __syncthreads();

        int tn = t + S_SPLIT;
        if (tn < ntiles) {
            uint32_t koff = (buf ^ 1) ? 0x4200u : 0u;   // 4224 floats
            uint32_t voff = (buf ^ 1) ? 0x4000u : 0u;   // 4096 floats
            const float* gk = gkb + (tn << 5) * 128;
            const float* gv = gvb + (tn << 5) * 128;
#pragma unroll
            for (int j = 0; j < 4; j++) {
                cp16(ku0 + koff + j * 128u, gk + (j << 3) * 4);
                cp16(vu0 + voff + j * 128u, gv + (j << 3) * 4);
            }
        }
        CP_COMMIT();

        // ---- score for k = (t<<5) + lane, q row q0 + w ----
        const float* ksp = sm + buf * 4224 + lane * KP;
        const float* qsp = qs + w * 128;
        float s = 0.f;
#pragma unroll
        for (int h = 0; h < 128; h += 4) {
            float4 kv = *(float4*)&ksp[h];
            float4 qv = *(float4*)&qsp[h];
            float4 w4 = *(float4*)&wv[h];
            s += fast_tanh(qv.x + kv.x) * w4.x;
            s += fast_tanh(qv.y + kv.y) * w4.y;
            s += fast_tanh(qv.z + kv.z) * w4.z;
            s += fast_tanh(qv.w + kv.w) * w4.w;
        }
        if ((t << 5) + lane >= nv) s = NEG_FILL;   // exp -> exactly 0

        float p = __expf(s);
        l += p;

        // ---- AV: lane owns output dims lane*4 .. lane*4+3 ----
        const float* vsp = sm + 8448 + buf * 4096;
#pragma unroll
        for (int k = 0; k < KT; k++) {
            float  pk = __shfl_sync(0xffffffffu, p, k);
            float4 vv = *(float4*)&vsp[k * 128 + (lane << 2)];
            o.x += pk * vv.x; o.y += pk * vv.y;
            o.z += pk * vv.z; o.w += pk * vv.w;
        }
    }

#pragma unroll
    for (int off = 16; off; off >>= 1)
        l += __shfl_xor_sync(0xffffffffu, l, off);

    int row = (b << 8) + q0 + w;
    if (lane == 0) g_pl[sp * 2048 + row] = l;
    *(float4*)&g_po[(sp * 2048 + row) * 128 + (lane << 2)] = o;
}

// ----------------------------------------------------------------------------
// Combine partials: out[row,:] = sum_s o_s / sum_s l_s
// ----------------------------------------------------------------------------
__global__ __launch_bounds__(256) void combine_kernel(float* __restrict__ out)
{
    int idx = blockIdx.x * 256 + threadIdx.x;   // 0 .. 65535
    int row = idx >> 5;
    int c   = (idx & 31) << 2;

    float  l = 0.f;
    float4 a = {0.f, 0.f, 0.f, 0.f};
#pragma unroll
    for (int s = 0; s < S_SPLIT; s++) {
        l += g_pl[s * 2048 + row];
        float4 v = *(const float4*)&g_po[(s * 2048 + row) * 128 + c];
        a.x += v.x; a.y += v.y; a.z += v.z; a.w += v.w;
    }
    float inv = 1.0f / l;
    a.x *= inv; a.y *= inv; a.z *= inv; a.w *= inv;
    *(float4*)&out[row * 128 + c] = a;
}

// ----------------------------------------------------------------------------
// Launch
// ----------------------------------------------------------------------------
extern "C" void kernel_launch(void* const* d_in, const int* in_sizes, int n_in,
                              void* d_out, int out_size)
{
    const float* queries    = (const float*)d_in[0];  // [8,256,256]
    const float* keys       = (const float*)d_in[1];  // [8,1024,256]
    const float* values     = (const float*)d_in[2];  // [8,1024,128]
    const int*   valid_lens = (const int*)  d_in[3];  // [8]
    const float* W_q        = (const float*)d_in[4];  // [256,128]
    const float* W_k        = (const float*)d_in[5];  // [256,128]
    const float* w_v        = (const float*)d_in[6];  // [128]
    float*       out        = (float*)d_out;          // [8,256,128]

    cudaFuncSetAttribute(attn_partial_kernel,
                         cudaFuncAttributeMaxDynamicSharedMemorySize,
                         ATTN_SMEM_BYTES);

    proj_kernel<<<160, 512>>>(queries, keys, W_q, W_k, valid_lens);

    dim3 grid(256 / QT, 8, S_SPLIT);
    attn_partial_kernel<<<grid, 256, ATTN_SMEM_BYTES>>>(values, valid_lens, w_v);

    combine_kernel<<<256, 256>>>(out);
}

// round 7
// speedup vs baseline: 1.4159x; 1.1705x over previous
#include <cuda_runtime.h>
#include <cstdint>

// ============================================================================
// AdditiveAttention fused kernels for GB300 (sm_103a) — Round 6
//   proj: 4x4 microtile (A broadcast + conflict-free B) -> FFMA-bound
//   attn: 2 q-rows per warp (QT=16) -> halves K/V smem traffic per row
// ============================================================================

#define NEG_FILL (-1e6f)
#define S_SPLIT 8
#define QT 16
#define KT 32
#define KP 132

// Scratch (allocation-free: __device__ globals)
__device__ float g_qh[8 * 256 * 128];                 // 1 MB
__device__ float g_kh[8 * 1024 * 128];                // 4 MB
__device__ float g_po[S_SPLIT * 2048 * 128];          // 8 MB partial o
__device__ float g_pl[S_SPLIT * 2048];                // 64 KB partial l

__device__ __forceinline__ float fast_tanh(float x) {
    float y;
    asm("tanh.approx.f32 %0, %1;" : "=f"(y) : "f"(x));
    return y;
}
__device__ __forceinline__ void cp16(uint32_t s, const void* g) {
    asm volatile("cp.async.cg.shared.global [%0], [%1], 16;" :: "r"(s), "l"(g));
}
#define CP_COMMIT() asm volatile("cp.async.commit_group;")
#define CP_WAIT0()  asm volatile("cp.async.wait_group 0;")

// ----------------------------------------------------------------------------
// Projection GEMM: Y[rows,128] = X[rows,256] @ W[256,128]
// BM=64, BN=128, BK=16, 512 threads. 4x4 microtile:
//   ty = tid>>5 (0..15) -> rows ty*4..+3  (constant within warp -> A broadcast)
//   tx = tid&31 (0..31) -> cols tx*4..+3  (conflict-free LDS.128)
// Per warp per k-step: 5 crossbar phases for 16 FFMA -> FFMA-bound.
// blocks 0..31 -> q rows, 32..159 -> k rows (masked blocks exit).
// ----------------------------------------------------------------------------
__global__ __launch_bounds__(512) void proj_kernel(
    const float* __restrict__ Xq, const float* __restrict__ Xk,
    const float* __restrict__ Wq, const float* __restrict__ Wk,
    const int* __restrict__ valid_lens)
{
    int bx = blockIdx.x;
    const float* X; const float* W; float* Y; int row0;
    if (bx < 32) {
        X = Xq; W = Wq; Y = g_qh; row0 = bx << 6;
    } else {
        int kb = bx - 32;               // 0..127, 16 per batch
        int b  = kb >> 4;
        if (((kb & 15) << 6) >= valid_lens[b]) return;  // never read downstream
        X = Xk; W = Wk; Y = g_kh; row0 = kb << 6;
    }

    __shared__ float Xs[2][16][64];     // [buf][k][row] transposed, 8 KB
    __shared__ float Ws[2][16][128];    // [buf][k][col], 16 KB

    int tid = threadIdx.x;
    int tx = tid & 31;      // cols tx*4..+3
    int ty = tid >> 5;      // rows ty*4..+3 (== warp id)

    // load lane mapping
    int xr = tid >> 3;              // 0..63
    int xc = (tid & 7) << 1;        // 0..14 (even)
    int wr = tid >> 5;              // 0..15
    int wc = (tid & 31) << 2;       // 0..124

    const float* Xp = &X[(row0 + xr) * 256 + xc];
    const float* Wp = &W[wr * 128 + wc];

    float acc[4][4];
#pragma unroll
    for (int i = 0; i < 4; i++)
#pragma unroll
        for (int j = 0; j < 4; j++) acc[i][j] = 0.f;

    // prologue: tile 0 -> buf 0
    float2 xv = *(const float2*)Xp;
    float4 wv = *(const float4*)Wp;
    Xs[0][xc][xr] = xv.x; Xs[0][xc + 1][xr] = xv.y;
    *(float4*)&Ws[0][wr][wc] = wv;
    __syncthreads();

    for (int it = 0; it < 16; it++) {
        int buf = it & 1;
        if (it < 15) {  // prefetch next k-tile into registers
            int k0 = (it + 1) << 4;
            xv = *(const float2*)(Xp + k0);
            wv = *(const float4*)(Wp + k0 * 128);
        }
#pragma unroll
        for (int k = 0; k < 16; k++) {
            float4 a = *(float4*)&Xs[buf][k][ty * 4];   // broadcast (1 phase)
            float4 b = *(float4*)&Ws[buf][k][tx * 4];   // conflict-free (4 ph)
            float av[4] = {a.x, a.y, a.z, a.w};
            float bv[4] = {b.x, b.y, b.z, b.w};
#pragma unroll
            for (int i = 0; i < 4; i++)
#pragma unroll
                for (int j = 0; j < 4; j++)
                    acc[i][j] += av[i] * bv[j];
        }
        if (it < 15) {
            int nb = buf ^ 1;
            Xs[nb][xc][xr] = xv.x; Xs[nb][xc + 1][xr] = xv.y;
            *(float4*)&Ws[nb][wr][wc] = wv;
        }
        __syncthreads();
    }

#pragma unroll
    for (int i = 0; i < 4; i++) {
        int r = row0 + ty * 4 + i;
        float4 o = {acc[i][0], acc[i][1], acc[i][2], acc[i][3]};
        *(float4*)&Y[r * 128 + tx * 4] = o;
    }
}

// ----------------------------------------------------------------------------
// Split-K score + exp + AV partial kernel, cp.async double-buffered.
// grid = (Q/QT=16, B, S_SPLIT), 256 threads, 8 warps.
// Warp w handles q-rows 2w and 2w+1: one K/V smem read feeds two rows.
// Dynamic smem layout (floats):
//   ks[2][32][132] @ 0        (8448)
//   vs[2][32][128] @ 8448     (8192)
//   qs[16][128]    @ 16640    (2048)
//   wv[128]        @ 18688    (128)    total 18816 floats = 75264 B
// ----------------------------------------------------------------------------
#define ATTN_SMEM_BYTES 75264

__global__ __launch_bounds__(256) void attn_partial_kernel(
    const float* __restrict__ V, const int* __restrict__ valid_lens,
    const float* __restrict__ w_v)
{
    extern __shared__ float sm[];
    float* qs = sm + 16640;
    float* wv = sm + 18688;

    int b    = blockIdx.y;
    int q0   = blockIdx.x * QT;
    int sp   = blockIdx.z;
    int tid  = threadIdx.x;
    int w    = tid >> 5;
    int lane = tid & 31;
    int nv   = valid_lens[b];          // 1..1024
    int ntiles = (nv + 31) >> 5;

    uint32_t su = (uint32_t)__cvta_generic_to_shared(sm);

    int lr = tid >> 3;                 // 0..31
    int lc = (tid & 7) << 2;           // float col base
    const float* gkb = g_kh + ((size_t)(b << 10) + lr) * 128 + lc;
    const float* gvb = V    + ((size_t)(b << 10) + lr) * 128 + lc;
    uint32_t ku0 = su + (uint32_t)(lr * KP  + lc) * 4u;
    uint32_t vu0 = su + (uint32_t)(8448 + lr * 128 + lc) * 4u;

    // prologue: issue tile sp into buf 0
    if (sp < ntiles) {
        const float* gk = gkb + (sp << 5) * 128;
        const float* gv = gvb + (sp << 5) * 128;
#pragma unroll
        for (int j = 0; j < 4; j++) {
            cp16(ku0 + j * 128u, gk + (j << 3) * 4);
            cp16(vu0 + j * 128u, gv + (j << 3) * 4);
        }
    }
    CP_COMMIT();

    // stage 16 q rows + w_v (overlaps with cp.async)
    {
        int r = tid >> 4;              // 0..15
        int c = (tid & 15) << 3;       // 0,8,...,120
        const float* src = &g_qh[((b << 8) + q0 + r) * 128 + c];
        *(float4*)&qs[r * 128 + c]     = *(const float4*)(src);
        *(float4*)&qs[r * 128 + c + 4] = *(const float4*)(src + 4);
    }
    if (tid < 128) wv[tid] = w_v[tid];

    float  l0 = 0.f, l1 = 0.f;
    float4 o0 = {0.f, 0.f, 0.f, 0.f};
    float4 o1 = {0.f, 0.f, 0.f, 0.f};

    const float* qsp0 = qs + (2 * w)     * 128;
    const float* qsp1 = qs + (2 * w + 1) * 128;

    int buf = 0;
    for (int t = sp; t < ntiles; t += S_SPLIT, buf ^= 1) {
        CP_WAIT0();
        __syncthreads();

        int tn = t + S_SPLIT;
        if (tn < ntiles) {
            uint32_t koff = (buf ^ 1) ? 0x4200u : 0u;   // bytes: 4224 floats
            uint32_t voff = (buf ^ 1) ? 0x4000u : 0u;   // bytes: 4096 floats
            const float* gk = gkb + (tn << 5) * 128;
            const float* gv = gvb + (tn << 5) * 128;
#pragma unroll
            for (int j = 0; j < 4; j++) {
                cp16(ku0 + koff + j * 128u, gk + (j << 3) * 4);
                cp16(vu0 + voff + j * 128u, gv + (j << 3) * 4);
            }
        }
        CP_COMMIT();

        // ---- scores for k = (t<<5) + lane, q rows 2w and 2w+1 ----
        const float* ksp = sm + buf * 4224 + lane * KP;
        float s0 = 0.f, s1 = 0.f;
#pragma unroll
        for (int h = 0; h < 128; h += 4) {
            float4 kv = *(float4*)&ksp[h];
            float4 w4 = *(float4*)&wv[h];
            float4 qa = *(float4*)&qsp0[h];
            float4 qb = *(float4*)&qsp1[h];
            s0 += fast_tanh(qa.x + kv.x) * w4.x;
            s1 += fast_tanh(qb.x + kv.x) * w4.x;
            s0 += fast_tanh(qa.y + kv.y) * w4.y;
            s1 += fast_tanh(qb.y + kv.y) * w4.y;
            s0 += fast_tanh(qa.z + kv.z) * w4.z;
            s1 += fast_tanh(qb.z + kv.z) * w4.z;
            s0 += fast_tanh(qa.w + kv.w) * w4.w;
            s1 += fast_tanh(qb.w + kv.w) * w4.w;
        }
        if ((t << 5) + lane >= nv) { s0 = NEG_FILL; s1 = NEG_FILL; }

        float p0 = __expf(s0);
        float p1 = __expf(s1);
        l0 += p0; l1 += p1;

        // ---- AV: one V read feeds both rows ----
        const float* vsp = sm + 8448 + buf * 4096;
#pragma unroll
        for (int k = 0; k < KT; k++) {
            float  pa = __shfl_sync(0xffffffffu, p0, k);
            float  pb = __shfl_sync(0xffffffffu, p1, k);
            float4 vv = *(float4*)&vsp[k * 128 + (lane << 2)];
            o0.x += pa * vv.x; o0.y += pa * vv.y;
            o0.z += pa * vv.z; o0.w += pa * vv.w;
            o1.x += pb * vv.x; o1.y += pb * vv.y;
            o1.z += pb * vv.z; o1.w += pb * vv.w;
        }
    }

#pragma unroll
    for (int off = 16; off; off >>= 1) {
        l0 += __shfl_xor_sync(0xffffffffu, l0, off);
        l1 += __shfl_xor_sync(0xffffffffu, l1, off);
    }

    int row0 = (b << 8) + q0 + 2 * w;
    if (lane == 0) {
        g_pl[sp * 2048 + row0]     = l0;
        g_pl[sp * 2048 + row0 + 1] = l1;
    }
    *(float4*)&g_po[(sp * 2048 + row0) * 128 + (lane << 2)]       = o0;
    *(float4*)&g_po[(sp * 2048 + row0 + 1) * 128 + (lane << 2)]   = o1;
}

// ----------------------------------------------------------------------------
// Combine partials: out[row,:] = sum_s o_s / sum_s l_s
// ----------------------------------------------------------------------------
__global__ __launch_bounds__(256) void combine_kernel(float* __restrict__ out)
{
    int idx = blockIdx.x * 256 + threadIdx.x;   // 0 .. 65535
    int row = idx >> 5;
    int c   = (idx & 31) << 2;

    float  l = 0.f;
    float4 a = {0.f, 0.f, 0.f, 0.f};
#pragma unroll
    for (int s = 0; s < S_SPLIT; s++) {
        l += g_pl[s * 2048 + row];
        float4 v = *(const float4*)&g_po[(s * 2048 + row) * 128 + c];
        a.x += v.x; a.y += v.y; a.z += v.z; a.w += v.w;
    }
    float inv = 1.0f / l;
    a.x *= inv; a.y *= inv; a.z *= inv; a.w *= inv;
    *(float4*)&out[row * 128 + c] = a;
}

// ----------------------------------------------------------------------------
// Launch
// ----------------------------------------------------------------------------
extern "C" void kernel_launch(void* const* d_in, const int* in_sizes, int n_in,
                              void* d_out, int out_size)
{
    const float* queries    = (const float*)d_in[0];  // [8,256,256]
    const float* keys       = (const float*)d_in[1];  // [8,1024,256]
    const float* values     = (const float*)d_in[2];  // [8,1024,128]
    const int*   valid_lens = (const int*)  d_in[3];  // [8]
    const float* W_q        = (const float*)d_in[4];  // [256,128]
    const float* W_k        = (const float*)d_in[5];  // [256,128]
    const float* w_v        = (const float*)d_in[6];  // [128]
    float*       out        = (float*)d_out;          // [8,256,128]

    cudaFuncSetAttribute(attn_partial_kernel,
                         cudaFuncAttributeMaxDynamicSharedMemorySize,
                         ATTN_SMEM_BYTES);

    proj_kernel<<<160, 512>>>(queries, keys, W_q, W_k, valid_lens);

    dim3 grid(256 / QT, 8, S_SPLIT);
    attn_partial_kernel<<<grid, 256, ATTN_SMEM_BYTES>>>(values, valid_lens, w_v);

    combine_kernel<<<256, 256>>>(out);
}